// round 1
// baseline (speedup 1.0000x reference)
#include <cuda_runtime.h>
#include <math.h>

// Problem constants
#define T_DIM 2048
#define B_DIM 8
#define F_DIM 768
#define H_DIM 3
#define DH    256
#define M_ROWS (T_DIM * B_DIM)   // 16384

// Scratch (allocation-free: device globals)
__device__ float g_Q[T_DIM * B_DIM * F_DIM];
__device__ float g_K[T_DIM * B_DIM * F_DIM];
__device__ float g_V[T_DIM * B_DIM * F_DIM];
__device__ float g_O[T_DIM * B_DIM * F_DIM];

// ---------------------------------------------------------------------------
// GEMM: C[m,n] = sum_k A[m,k] * W[n,k] + bias[n]   (torch Linear: x @ W.T + b)
// BM=128, BN=64, BK=16, 256 threads, 8x4 per-thread microtile.
// ---------------------------------------------------------------------------
__global__ __launch_bounds__(256) void gemm_bias_kernel(
    const float* __restrict__ A, const float* __restrict__ W,
    const float* __restrict__ bias, float* __restrict__ C,
    int M, int N, int K)
{
    __shared__ float As[16][132];  // [k][m], padded
    __shared__ float Bs[16][68];   // [k][n], padded

    const int tid = threadIdx.x;
    const int tx = tid & 15;       // n direction (x4)
    const int ty = tid >> 4;       // m direction (x8)
    const int m0 = blockIdx.y * 128;
    const int n0 = blockIdx.x * 64;

    float acc[8][4];
#pragma unroll
    for (int i = 0; i < 8; i++)
#pragma unroll
        for (int j = 0; j < 4; j++) acc[i][j] = 0.f;

    for (int k0 = 0; k0 < K; k0 += 16) {
        // Load A tile: 128 rows x 16 -> 512 float4, 2 per thread
#pragma unroll
        for (int l = 0; l < 2; l++) {
            int idx = tid + l * 256;
            int row = idx >> 2, c = idx & 3;
            float4 a = *(const float4*)&A[(size_t)(m0 + row) * K + k0 + c * 4];
            As[c * 4 + 0][row] = a.x;
            As[c * 4 + 1][row] = a.y;
            As[c * 4 + 2][row] = a.z;
            As[c * 4 + 3][row] = a.w;
        }
        // Load B tile: 64 rows x 16 -> 256 float4, 1 per thread
        {
            int row = tid >> 2, c = tid & 3;
            float4 b = *(const float4*)&W[(size_t)(n0 + row) * K + k0 + c * 4];
            Bs[c * 4 + 0][row] = b.x;
            Bs[c * 4 + 1][row] = b.y;
            Bs[c * 4 + 2][row] = b.z;
            Bs[c * 4 + 3][row] = b.w;
        }
        __syncthreads();

#pragma unroll
        for (int kk = 0; kk < 16; kk++) {
            float4 a0 = *(const float4*)&As[kk][ty * 8];
            float4 a1 = *(const float4*)&As[kk][ty * 8 + 4];
            float4 b0 = *(const float4*)&Bs[kk][tx * 4];
            float a[8] = {a0.x, a0.y, a0.z, a0.w, a1.x, a1.y, a1.z, a1.w};
            float b[4] = {b0.x, b0.y, b0.z, b0.w};
#pragma unroll
            for (int i = 0; i < 8; i++)
#pragma unroll
                for (int j = 0; j < 4; j++) acc[i][j] += a[i] * b[j];
        }
        __syncthreads();
    }

    float4 bb = *(const float4*)&bias[n0 + tx * 4];
#pragma unroll
    for (int i = 0; i < 8; i++) {
        float4 o;
        o.x = acc[i][0] + bb.x;
        o.y = acc[i][1] + bb.y;
        o.z = acc[i][2] + bb.z;
        o.w = acc[i][3] + bb.w;
        *(float4*)&C[(size_t)(m0 + ty * 8 + i) * N + n0 + tx * 4] = o;
    }
}

// ---------------------------------------------------------------------------
// Flash attention: per (b,h), Br=32 query rows per block, Bc=32 key rows per
// iteration, dh=256. Thread (q = tid/8, sub = tid&7):
//   - score phase: computes keys k = sub + 8*i (i<4), full-256 dot vs Qs row
//   - softmax stats via shfl within the 8-lane row group
//   - PV phase: owns output dims d in [sub*32, sub*32+32)
// V tile swizzled (+4 floats per 32) so PV LDS.128 across sub is conflict-free.
// ---------------------------------------------------------------------------
#define QK_STRIDE 260
#define V_STRIDE  288
#define ATTN_SMEM_FLOATS (2 * 32 * QK_STRIDE + 32 * V_STRIDE + 32 * 32)
#define ATTN_SMEM_BYTES  (ATTN_SMEM_FLOATS * 4)

__global__ __launch_bounds__(256) void attn_kernel(
    const float* __restrict__ Q, const float* __restrict__ K,
    const float* __restrict__ V, float* __restrict__ O)
{
    extern __shared__ float sm[];
    float* Qs = sm;                          // 32 x 260
    float* Ks = sm + 32 * QK_STRIDE;         // 32 x 260
    float* Vs = sm + 64 * QK_STRIDE;         // 32 x 288 (swizzled)
    float* P  = sm + 64 * QK_STRIDE + 32 * V_STRIDE;  // 32 x 32

    const int tid = threadIdx.x;
    const int q   = tid >> 3;
    const int sub = tid & 7;
    const int bh = blockIdx.y;
    const int b  = bh / H_DIM;
    const int h  = bh % H_DIM;
    const int t0 = blockIdx.x * 32;

    // global row base for token t, batch b, head h
    const size_t head_off = (size_t)b * F_DIM + (size_t)h * DH;
    const size_t row_stride = (size_t)B_DIM * F_DIM;  // 6144

    // Load Q tile (32 rows x 64 float4)
    for (int idx = tid; idx < 32 * 64; idx += 256) {
        int r = idx >> 6, c = idx & 63;
        float4 v = *(const float4*)&Q[(size_t)(t0 + r) * row_stride + head_off + c * 4];
        *(float4*)&Qs[r * QK_STRIDE + c * 4] = v;
    }
    __syncthreads();

    float m_run = -1e30f, l_run = 0.f;
    float acc[32];
#pragma unroll
    for (int j = 0; j < 32; j++) acc[j] = 0.f;

    for (int s0 = 0; s0 < T_DIM; s0 += 32) {
        // Load K and V tiles
        for (int idx = tid; idx < 32 * 64; idx += 256) {
            int r = idx >> 6, c = idx & 63;
            size_t g = (size_t)(s0 + r) * row_stride + head_off + c * 4;
            float4 kk = *(const float4*)&K[g];
            *(float4*)&Ks[r * QK_STRIDE + c * 4] = kk;
            float4 vv = *(const float4*)&V[g];
            // swizzle: element d stored at d + (d>>5)*4 ; d = c*4 -> c*4 + (c>>3)*4
            *(float4*)&Vs[r * V_STRIDE + c * 4 + (c >> 3) * 4] = vv;
        }
        __syncthreads();

        // --- scores for keys sub + 8*i ---
        float sv[4];
        const float* qr = &Qs[q * QK_STRIDE];
#pragma unroll
        for (int i = 0; i < 4; i++) {
            const float* kr = &Ks[(sub + 8 * i) * QK_STRIDE];
            float d0 = 0.f, d1 = 0.f, d2 = 0.f, d3 = 0.f;
#pragma unroll
            for (int d = 0; d < DH; d += 4) {
                float4 qq = *(const float4*)&qr[d];
                float4 kk = *(const float4*)&kr[d];
                d0 += qq.x * kk.x; d1 += qq.y * kk.y;
                d2 += qq.z * kk.z; d3 += qq.w * kk.w;
            }
            sv[i] = (d0 + d1 + d2 + d3) * 0.125f;
        }

        // --- online softmax stats (8-lane group = one query row) ---
        float tmax = fmaxf(fmaxf(sv[0], sv[1]), fmaxf(sv[2], sv[3]));
#pragma unroll
        for (int o = 1; o < 8; o <<= 1)
            tmax = fmaxf(tmax, __shfl_xor_sync(0xffffffffu, tmax, o));
        float m_new = fmaxf(m_run, tmax);
        float alpha = __expf(m_run - m_new);
        float p[4];
        float ls = 0.f;
#pragma unroll
        for (int i = 0; i < 4; i++) { p[i] = __expf(sv[i] - m_new); ls += p[i]; }
#pragma unroll
        for (int o = 1; o < 8; o <<= 1)
            ls += __shfl_xor_sync(0xffffffffu, ls, o);
        l_run = l_run * alpha + ls;
        m_run = m_new;

#pragma unroll
        for (int i = 0; i < 4; i++) P[q * 32 + sub + 8 * i] = p[i];
        __syncwarp();

        // --- PV accumulate: dims d = sub*32 + j ---
#pragma unroll
        for (int j = 0; j < 32; j++) acc[j] *= alpha;

#pragma unroll 2
        for (int k4 = 0; k4 < 8; k4++) {
            float4 pp = *(const float4*)&P[q * 32 + k4 * 4];
            float pk[4] = {pp.x, pp.y, pp.z, pp.w};
#pragma unroll
            for (int ki = 0; ki < 4; ki++) {
                const int k = k4 * 4 + ki;
                const float* vr = &Vs[k * V_STRIDE + sub * 36];  // swizzled base
                float pv = pk[ki];
#pragma unroll
                for (int j4 = 0; j4 < 8; j4++) {
                    float4 vv = *(const float4*)&vr[j4 * 4];
                    acc[j4 * 4 + 0] += pv * vv.x;
                    acc[j4 * 4 + 1] += pv * vv.y;
                    acc[j4 * 4 + 2] += pv * vv.z;
                    acc[j4 * 4 + 3] += pv * vv.w;
                }
            }
        }
        __syncthreads();
    }

    // Epilogue: normalize and write O
    const float inv_l = 1.f / l_run;
    const size_t ob = (size_t)(t0 + q) * row_stride + head_off + sub * 32;
#pragma unroll
    for (int j4 = 0; j4 < 8; j4++) {
        float4 o;
        o.x = acc[j4 * 4 + 0] * inv_l;
        o.y = acc[j4 * 4 + 1] * inv_l;
        o.z = acc[j4 * 4 + 2] * inv_l;
        o.w = acc[j4 * 4 + 3] * inv_l;
        *(float4*)&O[ob + j4 * 4] = o;
    }
}

// ---------------------------------------------------------------------------
extern "C" void kernel_launch(void* const* d_in, const int* in_sizes, int n_in,
                              void* d_out, int out_size)
{
    const float* x  = (const float*)d_in[0];
    const float* Wq = (const float*)d_in[1];
    const float* bq = (const float*)d_in[2];
    const float* Wk = (const float*)d_in[3];
    const float* bk = (const float*)d_in[4];
    const float* Wv = (const float*)d_in[5];
    const float* bv = (const float*)d_in[6];
    const float* Wo = (const float*)d_in[7];
    const float* bo = (const float*)d_in[8];
    float* out = (float*)d_out;

    float *Qp, *Kp, *Vp, *Op;
    cudaGetSymbolAddress((void**)&Qp, g_Q);
    cudaGetSymbolAddress((void**)&Kp, g_K);
    cudaGetSymbolAddress((void**)&Vp, g_V);
    cudaGetSymbolAddress((void**)&Op, g_O);

    dim3 ggrid(F_DIM / 64, M_ROWS / 128);   // (12, 128)

    gemm_bias_kernel<<<ggrid, 256>>>(x, Wq, bq, Qp, M_ROWS, F_DIM, F_DIM);
    gemm_bias_kernel<<<ggrid, 256>>>(x, Wk, bk, Kp, M_ROWS, F_DIM, F_DIM);
    gemm_bias_kernel<<<ggrid, 256>>>(x, Wv, bv, Vp, M_ROWS, F_DIM, F_DIM);

    cudaFuncSetAttribute(attn_kernel,
                         cudaFuncAttributeMaxDynamicSharedMemorySize,
                         ATTN_SMEM_BYTES);
    attn_kernel<<<dim3(T_DIM / 32, B_DIM * H_DIM), 256, ATTN_SMEM_BYTES>>>(
        Qp, Kp, Vp, Op);

    gemm_bias_kernel<<<ggrid, 256>>>(Op, Wo, bo, out, M_ROWS, F_DIM, F_DIM);
}

// round 2
// speedup vs baseline: 3.1262x; 3.1262x over previous
#include <cuda_runtime.h>
#include <math.h>
#include <stdint.h>

// Problem constants
#define T_DIM 2048
#define B_DIM 8
#define F_DIM 768
#define H_DIM 3
#define DH    256
#define M_ROWS (T_DIM * B_DIM)   // 16384
#define ROW_STRIDE 6144          // B_DIM * F_DIM

// Scratch (allocation-free: device globals)
__device__ float g_Q[T_DIM * B_DIM * F_DIM];
__device__ float g_K[T_DIM * B_DIM * F_DIM];
__device__ float g_V[T_DIM * B_DIM * F_DIM];
__device__ float g_O[T_DIM * B_DIM * F_DIM];

// ---------------------------------------------------------------------------
// tf32 helpers
// ---------------------------------------------------------------------------
__device__ __forceinline__ float to_tf32(float x) {
    uint32_t u;
    asm("cvt.rna.tf32.f32 %0, %1;" : "=r"(u) : "f"(x));
    return __uint_as_float(u);
}

__device__ __forceinline__ void mma8(float c[4],
                                     uint32_t a0, uint32_t a1, uint32_t a2, uint32_t a3,
                                     uint32_t b0, uint32_t b1) {
    asm volatile(
        "mma.sync.aligned.m16n8k8.row.col.f32.tf32.tf32.f32 "
        "{%0,%1,%2,%3}, {%4,%5,%6,%7}, {%8,%9}, {%0,%1,%2,%3};"
        : "+f"(c[0]), "+f"(c[1]), "+f"(c[2]), "+f"(c[3])
        : "r"(a0), "r"(a1), "r"(a2), "r"(a3), "r"(b0), "r"(b1));
}

// ---------------------------------------------------------------------------
// GEMM: C[m,n] = sum_k A[m,k] * W[n,k] + bias[n]   (torch Linear: x @ W.T + b)
// BM=128, BN=64, BK=16, 256 threads, 8x4 per-thread microtile. (unchanged)
// ---------------------------------------------------------------------------
__global__ __launch_bounds__(256) void gemm_bias_kernel(
    const float* __restrict__ A, const float* __restrict__ W,
    const float* __restrict__ bias, float* __restrict__ C,
    int M, int N, int K)
{
    __shared__ float As[16][132];  // [k][m], padded
    __shared__ float Bs[16][68];   // [k][n], padded

    const int tid = threadIdx.x;
    const int tx = tid & 15;       // n direction (x4)
    const int ty = tid >> 4;       // m direction (x8)
    const int m0 = blockIdx.y * 128;
    const int n0 = blockIdx.x * 64;

    float acc[8][4];
#pragma unroll
    for (int i = 0; i < 8; i++)
#pragma unroll
        for (int j = 0; j < 4; j++) acc[i][j] = 0.f;

    for (int k0 = 0; k0 < K; k0 += 16) {
#pragma unroll
        for (int l = 0; l < 2; l++) {
            int idx = tid + l * 256;
            int row = idx >> 2, c = idx & 3;
            float4 a = *(const float4*)&A[(size_t)(m0 + row) * K + k0 + c * 4];
            As[c * 4 + 0][row] = a.x;
            As[c * 4 + 1][row] = a.y;
            As[c * 4 + 2][row] = a.z;
            As[c * 4 + 3][row] = a.w;
        }
        {
            int row = tid >> 2, c = tid & 3;
            float4 b = *(const float4*)&W[(size_t)(n0 + row) * K + k0 + c * 4];
            Bs[c * 4 + 0][row] = b.x;
            Bs[c * 4 + 1][row] = b.y;
            Bs[c * 4 + 2][row] = b.z;
            Bs[c * 4 + 3][row] = b.w;
        }
        __syncthreads();

#pragma unroll
        for (int kk = 0; kk < 16; kk++) {
            float4 a0 = *(const float4*)&As[kk][ty * 8];
            float4 a1 = *(const float4*)&As[kk][ty * 8 + 4];
            float4 b0 = *(const float4*)&Bs[kk][tx * 4];
            float a[8] = {a0.x, a0.y, a0.z, a0.w, a1.x, a1.y, a1.z, a1.w};
            float b[4] = {b0.x, b0.y, b0.z, b0.w};
#pragma unroll
            for (int i = 0; i < 8; i++)
#pragma unroll
                for (int j = 0; j < 4; j++) acc[i][j] += a[i] * b[j];
        }
        __syncthreads();
    }

    float4 bb = *(const float4*)&bias[n0 + tx * 4];
#pragma unroll
    for (int i = 0; i < 8; i++) {
        float4 o;
        o.x = acc[i][0] + bb.x;
        o.y = acc[i][1] + bb.y;
        o.z = acc[i][2] + bb.z;
        o.w = acc[i][3] + bb.w;
        *(float4*)&C[(size_t)(m0 + ty * 8 + i) * N + n0 + tx * 4] = o;
    }
}

// ---------------------------------------------------------------------------
// Tensor-core flash attention (tf32 mma.sync.m16n8k8).
// Block: 256 threads (8 warps, 4x2 warp grid). Br=64 q rows, Bc=64 keys/iter,
// dh=256. Per warp: S tile 16x32, O tile 16x128.
// smem strides picked so every fragment load is bank-conflict-free:
//   Q/K stride 260 (== 4 mod 32), V stride 264 (== 8 mod 32), P stride 68.
// ---------------------------------------------------------------------------
#define QK_STR 260
#define V_STR  264
#define P_STR  68
#define ATTN_SMEM_FLOATS (2 * 64 * QK_STR + 64 * V_STR + 64 * P_STR + 192)
#define ATTN_SMEM_BYTES  (ATTN_SMEM_FLOATS * 4)

__global__ __launch_bounds__(256) void attn_tc_kernel(
    const float* __restrict__ Q, const float* __restrict__ K,
    const float* __restrict__ V, float* __restrict__ O)
{
    extern __shared__ float sm[];
    float* Qs   = sm;                      // 64 x 260
    float* Ks   = Qs + 64 * QK_STR;        // 64 x 260
    float* Vs   = Ks + 64 * QK_STR;        // 64 x 264
    float* Ps   = Vs + 64 * V_STR;         // 64 x 68
    float* sm_m = Ps + 64 * P_STR;         // 64
    float* sm_l = sm_m + 64;               // 64
    float* sm_a = sm_l + 64;               // 64

    const int tid  = threadIdx.x;
    const int lane = tid & 31;
    const int w    = tid >> 5;
    const int g    = lane >> 2;   // 0..7
    const int tg   = lane & 3;    // 0..3
    const int wr   = w >> 1;      // 0..3
    const int wc   = w & 1;       // 0..1

    const int bh = blockIdx.y;
    const int b  = bh / H_DIM;
    const int h  = bh % H_DIM;
    const int t0 = blockIdx.x * 64;
    const size_t head = (size_t)b * F_DIM + (size_t)h * DH;

    if (tid < 64) { sm_m[tid] = -1e30f; sm_l[tid] = 0.f; }

    // Load Q tile (64 rows x 64 float4), convert to tf32
#pragma unroll
    for (int i = 0; i < 16; i++) {
        int idx = tid + i * 256;
        int r = idx >> 6, c = idx & 63;
        float4 v = *(const float4*)&Q[(size_t)(t0 + r) * ROW_STRIDE + head + c * 4];
        v.x = to_tf32(v.x); v.y = to_tf32(v.y);
        v.z = to_tf32(v.z); v.w = to_tf32(v.w);
        *(float4*)&Qs[r * QK_STR + c * 4] = v;
    }

    float oacc[16][4];
#pragma unroll
    for (int nt = 0; nt < 16; nt++)
#pragma unroll
        for (int j = 0; j < 4; j++) oacc[nt][j] = 0.f;

    const int rq = wr * 16, ck = wc * 32;   // S tile origin
    const int ro = wr * 16, co = wc * 128;  // O tile origin

    for (int s0 = 0; s0 < T_DIM; s0 += 64) {
        __syncthreads();  // prev PV done reading Vs/Ps (also covers Q-load/stat init)

        // Load K, V tiles (tf32)
#pragma unroll
        for (int i = 0; i < 16; i++) {
            int idx = tid + i * 256;
            int r = idx >> 6, c = idx & 63;
            size_t gaddr = (size_t)(s0 + r) * ROW_STRIDE + head + c * 4;
            float4 kk = *(const float4*)&K[gaddr];
            kk.x = to_tf32(kk.x); kk.y = to_tf32(kk.y);
            kk.z = to_tf32(kk.z); kk.w = to_tf32(kk.w);
            *(float4*)&Ks[r * QK_STR + c * 4] = kk;
            float4 vv = *(const float4*)&V[gaddr];
            vv.x = to_tf32(vv.x); vv.y = to_tf32(vv.y);
            vv.z = to_tf32(vv.z); vv.w = to_tf32(vv.w);
            *(float4*)&Vs[r * V_STR + c * 4] = vv;
        }
        __syncthreads();

        // ---- S = Q K^T  (warp tile 16x32) ----
        float sacc[4][4];
#pragma unroll
        for (int nt = 0; nt < 4; nt++)
#pragma unroll
            for (int j = 0; j < 4; j++) sacc[nt][j] = 0.f;

#pragma unroll 8
        for (int k0 = 0; k0 < DH; k0 += 8) {
            uint32_t a0 = __float_as_uint(Qs[(rq + g)     * QK_STR + k0 + tg]);
            uint32_t a1 = __float_as_uint(Qs[(rq + g + 8) * QK_STR + k0 + tg]);
            uint32_t a2 = __float_as_uint(Qs[(rq + g)     * QK_STR + k0 + tg + 4]);
            uint32_t a3 = __float_as_uint(Qs[(rq + g + 8) * QK_STR + k0 + tg + 4]);
#pragma unroll
            for (int nt = 0; nt < 4; nt++) {
                int n0 = ck + nt * 8;
                uint32_t b0 = __float_as_uint(Ks[(n0 + g) * QK_STR + k0 + tg]);
                uint32_t b1 = __float_as_uint(Ks[(n0 + g) * QK_STR + k0 + tg + 4]);
                mma8(sacc[nt], a0, a1, a2, a3, b0, b1);
            }
        }

        // store S tile to Ps (raw scores)
#pragma unroll
        for (int nt = 0; nt < 4; nt++) {
            int c0 = ck + nt * 8 + tg * 2;
            *(float2*)&Ps[(rq + g)     * P_STR + c0] = make_float2(sacc[nt][0], sacc[nt][1]);
            *(float2*)&Ps[(rq + g + 8) * P_STR + c0] = make_float2(sacc[nt][2], sacc[nt][3]);
        }
        __syncthreads();

        // ---- online softmax: row r handled by 4 threads (16 cols each) ----
        {
            int r = tid >> 2, qd = tid & 3;
            float* row = &Ps[r * P_STR + qd * 16];
            float4 v0 = *(float4*)&row[0];
            float4 v1 = *(float4*)&row[4];
            float4 v2 = *(float4*)&row[8];
            float4 v3 = *(float4*)&row[12];
            const float sc = 0.125f;
            v0.x *= sc; v0.y *= sc; v0.z *= sc; v0.w *= sc;
            v1.x *= sc; v1.y *= sc; v1.z *= sc; v1.w *= sc;
            v2.x *= sc; v2.y *= sc; v2.z *= sc; v2.w *= sc;
            v3.x *= sc; v3.y *= sc; v3.z *= sc; v3.w *= sc;

            float mx = fmaxf(fmaxf(fmaxf(v0.x, v0.y), fmaxf(v0.z, v0.w)),
                             fmaxf(fmaxf(v1.x, v1.y), fmaxf(v1.z, v1.w)));
            mx = fmaxf(mx, fmaxf(fmaxf(fmaxf(v2.x, v2.y), fmaxf(v2.z, v2.w)),
                                 fmaxf(fmaxf(v3.x, v3.y), fmaxf(v3.z, v3.w))));
            mx = fmaxf(mx, __shfl_xor_sync(0xffffffffu, mx, 1));
            mx = fmaxf(mx, __shfl_xor_sync(0xffffffffu, mx, 2));

            float m_old = sm_m[r];
            float m_new = fmaxf(m_old, mx);
            float alpha = __expf(m_old - m_new);

            v0.x = __expf(v0.x - m_new); v0.y = __expf(v0.y - m_new);
            v0.z = __expf(v0.z - m_new); v0.w = __expf(v0.w - m_new);
            v1.x = __expf(v1.x - m_new); v1.y = __expf(v1.y - m_new);
            v1.z = __expf(v1.z - m_new); v1.w = __expf(v1.w - m_new);
            v2.x = __expf(v2.x - m_new); v2.y = __expf(v2.y - m_new);
            v2.z = __expf(v2.z - m_new); v2.w = __expf(v2.w - m_new);
            v3.x = __expf(v3.x - m_new); v3.y = __expf(v3.y - m_new);
            v3.z = __expf(v3.z - m_new); v3.w = __expf(v3.w - m_new);

            float s = (v0.x + v0.y + v0.z + v0.w) + (v1.x + v1.y + v1.z + v1.w)
                    + (v2.x + v2.y + v2.z + v2.w) + (v3.x + v3.y + v3.z + v3.w);
            s += __shfl_xor_sync(0xffffffffu, s, 1);
            s += __shfl_xor_sync(0xffffffffu, s, 2);

            // write P back as tf32
            v0.x = to_tf32(v0.x); v0.y = to_tf32(v0.y); v0.z = to_tf32(v0.z); v0.w = to_tf32(v0.w);
            v1.x = to_tf32(v1.x); v1.y = to_tf32(v1.y); v1.z = to_tf32(v1.z); v1.w = to_tf32(v1.w);
            v2.x = to_tf32(v2.x); v2.y = to_tf32(v2.y); v2.z = to_tf32(v2.z); v2.w = to_tf32(v2.w);
            v3.x = to_tf32(v3.x); v3.y = to_tf32(v3.y); v3.z = to_tf32(v3.z); v3.w = to_tf32(v3.w);
            *(float4*)&row[0]  = v0;
            *(float4*)&row[4]  = v1;
            *(float4*)&row[8]  = v2;
            *(float4*)&row[12] = v3;

            if (qd == 0) {
                sm_m[r] = m_new;
                sm_l[r] = sm_l[r] * alpha + s;
                sm_a[r] = alpha;
            }
        }
        __syncthreads();

        // ---- rescale O, then O += P V  (warp tile 16x128) ----
        {
            float al0 = sm_a[ro + g];
            float al1 = sm_a[ro + g + 8];
#pragma unroll
            for (int nt = 0; nt < 16; nt++) {
                oacc[nt][0] *= al0; oacc[nt][1] *= al0;
                oacc[nt][2] *= al1; oacc[nt][3] *= al1;
            }
        }
#pragma unroll
        for (int k0 = 0; k0 < 64; k0 += 8) {
            uint32_t a0 = __float_as_uint(Ps[(ro + g)     * P_STR + k0 + tg]);
            uint32_t a1 = __float_as_uint(Ps[(ro + g + 8) * P_STR + k0 + tg]);
            uint32_t a2 = __float_as_uint(Ps[(ro + g)     * P_STR + k0 + tg + 4]);
            uint32_t a3 = __float_as_uint(Ps[(ro + g + 8) * P_STR + k0 + tg + 4]);
#pragma unroll
            for (int nt = 0; nt < 16; nt++) {
                int n0 = co + nt * 8;
                uint32_t b0 = __float_as_uint(Vs[(k0 + tg)     * V_STR + n0 + g]);
                uint32_t b1 = __float_as_uint(Vs[(k0 + tg + 4) * V_STR + n0 + g]);
                mma8(oacc[nt], a0, a1, a2, a3, b0, b1);
            }
        }
    }

    // ---- epilogue: normalize and write O ----
    {
        float il0 = 1.f / sm_l[ro + g];
        float il1 = 1.f / sm_l[ro + g + 8];
        size_t r0 = (size_t)(t0 + ro + g)     * ROW_STRIDE + head + co;
        size_t r1 = (size_t)(t0 + ro + g + 8) * ROW_STRIDE + head + co;
#pragma unroll
        for (int nt = 0; nt < 16; nt++) {
            int c0 = nt * 8 + tg * 2;
            *(float2*)&O[r0 + c0] = make_float2(oacc[nt][0] * il0, oacc[nt][1] * il0);
            *(float2*)&O[r1 + c0] = make_float2(oacc[nt][2] * il1, oacc[nt][3] * il1);
        }
    }
}

// ---------------------------------------------------------------------------
extern "C" void kernel_launch(void* const* d_in, const int* in_sizes, int n_in,
                              void* d_out, int out_size)
{
    const float* x  = (const float*)d_in[0];
    const float* Wq = (const float*)d_in[1];
    const float* bq = (const float*)d_in[2];
    const float* Wk = (const float*)d_in[3];
    const float* bk = (const float*)d_in[4];
    const float* Wv = (const float*)d_in[5];
    const float* bv = (const float*)d_in[6];
    const float* Wo = (const float*)d_in[7];
    const float* bo = (const float*)d_in[8];
    float* out = (float*)d_out;

    float *Qp, *Kp, *Vp, *Op;
    cudaGetSymbolAddress((void**)&Qp, g_Q);
    cudaGetSymbolAddress((void**)&Kp, g_K);
    cudaGetSymbolAddress((void**)&Vp, g_V);
    cudaGetSymbolAddress((void**)&Op, g_O);

    dim3 ggrid(F_DIM / 64, M_ROWS / 128);   // (12, 128)

    gemm_bias_kernel<<<ggrid, 256>>>(x, Wq, bq, Qp, M_ROWS, F_DIM, F_DIM);
    gemm_bias_kernel<<<ggrid, 256>>>(x, Wk, bk, Kp, M_ROWS, F_DIM, F_DIM);
    gemm_bias_kernel<<<ggrid, 256>>>(x, Wv, bv, Vp, M_ROWS, F_DIM, F_DIM);

    cudaFuncSetAttribute(attn_tc_kernel,
                         cudaFuncAttributeMaxDynamicSharedMemorySize,
                         ATTN_SMEM_BYTES);
    attn_tc_kernel<<<dim3(T_DIM / 64, B_DIM * H_DIM), 256, ATTN_SMEM_BYTES>>>(
        Qp, Kp, Vp, Op);

    gemm_bias_kernel<<<ggrid, 256>>>(Op, Wo, bo, out, M_ROWS, F_DIM, F_DIM);
}

// round 3
// speedup vs baseline: 3.4964x; 1.1184x over previous
#include <cuda_runtime.h>
#include <math.h>
#include <stdint.h>

// Problem constants
#define T_DIM 2048
#define B_DIM 8
#define F_DIM 768
#define H_DIM 3
#define DH    256
#define M_ROWS (T_DIM * B_DIM)   // 16384
#define ROW_STRIDE 6144          // B_DIM * F_DIM

// Scratch (allocation-free: device globals)
__device__ float g_Q[T_DIM * B_DIM * F_DIM];
__device__ float g_K[T_DIM * B_DIM * F_DIM];
__device__ float g_V[T_DIM * B_DIM * F_DIM];
__device__ float g_O[T_DIM * B_DIM * F_DIM];

// ---------------------------------------------------------------------------
// tf32 helpers
// ---------------------------------------------------------------------------
__device__ __forceinline__ float to_tf32(float x) {
    uint32_t u;
    asm("cvt.rna.tf32.f32 %0, %1;" : "=r"(u) : "f"(x));
    return __uint_as_float(u);
}

__device__ __forceinline__ void mma8(float c[4],
                                     uint32_t a0, uint32_t a1, uint32_t a2, uint32_t a3,
                                     uint32_t b0, uint32_t b1) {
    asm volatile(
        "mma.sync.aligned.m16n8k8.row.col.f32.tf32.tf32.f32 "
        "{%0,%1,%2,%3}, {%4,%5,%6,%7}, {%8,%9}, {%0,%1,%2,%3};"
        : "+f"(c[0]), "+f"(c[1]), "+f"(c[2]), "+f"(c[3])
        : "r"(a0), "r"(a1), "r"(a2), "r"(a3), "r"(b0), "r"(b1));
}

// ---------------------------------------------------------------------------
// 3xTF32 tensor-core GEMM: C[m,n] = sum_k A[m,k] * W[n,k] + bias[n]
// BM=128, BN=128, BK=16, 256 threads (8 warps, 4x2 grid), warp tile 32x64.
// A = Ah + Al, W = Wh + Wl (tf32 splits); C ≈ Ah·Wh + Ah·Wl + Al·Wh.
// smem stride 20 words -> all fragment loads bank-conflict-free.
// ---------------------------------------------------------------------------
#define GS 20   // smem row stride (words) for 16 K-columns + pad

__global__ __launch_bounds__(256, 2) void gemm_tc_kernel(
    const float* __restrict__ A, const float* __restrict__ W,
    const float* __restrict__ bias, float* __restrict__ C,
    int M, int N, int K)
{
    __shared__ float As_hi[128 * GS];
    __shared__ float As_lo[128 * GS];
    __shared__ float Bs_hi[128 * GS];
    __shared__ float Bs_lo[128 * GS];

    const int tid  = threadIdx.x;
    const int lane = tid & 31;
    const int w    = tid >> 5;
    const int g    = lane >> 2;   // 0..7
    const int tg   = lane & 3;    // 0..3
    const int wr   = w >> 1;      // 0..3 (m)
    const int wc   = w & 1;       // 0..1 (n)

    const int m0 = blockIdx.y * 128;
    const int n0 = blockIdx.x * 128;

    // loader mapping: 512 float4 per matrix tile, 2 per thread
    const int lrow0 = tid >> 2, lc = tid & 3;          // l=0
    const int lrow1 = (tid + 256) >> 2;                // l=1 (same lc)

    float4 pa0, pa1, pw0, pw1;
    pa0 = *(const float4*)&A[(size_t)(m0 + lrow0) * K + lc * 4];
    pa1 = *(const float4*)&A[(size_t)(m0 + lrow1) * K + lc * 4];
    pw0 = *(const float4*)&W[(size_t)(n0 + lrow0) * K + lc * 4];
    pw1 = *(const float4*)&W[(size_t)(n0 + lrow1) * K + lc * 4];

    float acc[2][8][4];
#pragma unroll
    for (int mi = 0; mi < 2; mi++)
#pragma unroll
        for (int nt = 0; nt < 8; nt++)
#pragma unroll
            for (int j = 0; j < 4; j++) acc[mi][nt][j] = 0.f;

    const int arow = wr * 32;        // warp A-row origin
    const int brow = wc * 64;        // warp B-row (n) origin

    for (int k0 = 0; k0 < K; k0 += 16) {
        // split + store staged tiles
        {
            float4 h, l;
            h.x = to_tf32(pa0.x); l.x = to_tf32(pa0.x - h.x);
            h.y = to_tf32(pa0.y); l.y = to_tf32(pa0.y - h.y);
            h.z = to_tf32(pa0.z); l.z = to_tf32(pa0.z - h.z);
            h.w = to_tf32(pa0.w); l.w = to_tf32(pa0.w - h.w);
            *(float4*)&As_hi[lrow0 * GS + lc * 4] = h;
            *(float4*)&As_lo[lrow0 * GS + lc * 4] = l;
            h.x = to_tf32(pa1.x); l.x = to_tf32(pa1.x - h.x);
            h.y = to_tf32(pa1.y); l.y = to_tf32(pa1.y - h.y);
            h.z = to_tf32(pa1.z); l.z = to_tf32(pa1.z - h.z);
            h.w = to_tf32(pa1.w); l.w = to_tf32(pa1.w - h.w);
            *(float4*)&As_hi[lrow1 * GS + lc * 4] = h;
            *(float4*)&As_lo[lrow1 * GS + lc * 4] = l;
            h.x = to_tf32(pw0.x); l.x = to_tf32(pw0.x - h.x);
            h.y = to_tf32(pw0.y); l.y = to_tf32(pw0.y - h.y);
            h.z = to_tf32(pw0.z); l.z = to_tf32(pw0.z - h.z);
            h.w = to_tf32(pw0.w); l.w = to_tf32(pw0.w - h.w);
            *(float4*)&Bs_hi[lrow0 * GS + lc * 4] = h;
            *(float4*)&Bs_lo[lrow0 * GS + lc * 4] = l;
            h.x = to_tf32(pw1.x); l.x = to_tf32(pw1.x - h.x);
            h.y = to_tf32(pw1.y); l.y = to_tf32(pw1.y - h.y);
            h.z = to_tf32(pw1.z); l.z = to_tf32(pw1.z - h.z);
            h.w = to_tf32(pw1.w); l.w = to_tf32(pw1.w - h.w);
            *(float4*)&Bs_hi[lrow1 * GS + lc * 4] = h;
            *(float4*)&Bs_lo[lrow1 * GS + lc * 4] = l;
        }
        __syncthreads();

        // prefetch next K tile
        if (k0 + 16 < K) {
            pa0 = *(const float4*)&A[(size_t)(m0 + lrow0) * K + k0 + 16 + lc * 4];
            pa1 = *(const float4*)&A[(size_t)(m0 + lrow1) * K + k0 + 16 + lc * 4];
            pw0 = *(const float4*)&W[(size_t)(n0 + lrow0) * K + k0 + 16 + lc * 4];
            pw1 = *(const float4*)&W[(size_t)(n0 + lrow1) * K + k0 + 16 + lc * 4];
        }

#pragma unroll
        for (int ks = 0; ks < 16; ks += 8) {
            uint32_t ah[2][4], al[2][4];
#pragma unroll
            for (int mi = 0; mi < 2; mi++) {
                int r0 = (arow + mi * 16 + g) * GS + ks + tg;
                int r1 = (arow + mi * 16 + g + 8) * GS + ks + tg;
                ah[mi][0] = __float_as_uint(As_hi[r0]);
                ah[mi][1] = __float_as_uint(As_hi[r1]);
                ah[mi][2] = __float_as_uint(As_hi[r0 + 4]);
                ah[mi][3] = __float_as_uint(As_hi[r1 + 4]);
                al[mi][0] = __float_as_uint(As_lo[r0]);
                al[mi][1] = __float_as_uint(As_lo[r1]);
                al[mi][2] = __float_as_uint(As_lo[r0 + 4]);
                al[mi][3] = __float_as_uint(As_lo[r1 + 4]);
            }
#pragma unroll
            for (int nt = 0; nt < 8; nt++) {
                int rb = (brow + nt * 8 + g) * GS + ks + tg;
                uint32_t bh0 = __float_as_uint(Bs_hi[rb]);
                uint32_t bh1 = __float_as_uint(Bs_hi[rb + 4]);
                uint32_t bl0 = __float_as_uint(Bs_lo[rb]);
                uint32_t bl1 = __float_as_uint(Bs_lo[rb + 4]);
#pragma unroll
                for (int mi = 0; mi < 2; mi++) {
                    mma8(acc[mi][nt], ah[mi][0], ah[mi][1], ah[mi][2], ah[mi][3], bh0, bh1);
                    mma8(acc[mi][nt], ah[mi][0], ah[mi][1], ah[mi][2], ah[mi][3], bl0, bl1);
                    mma8(acc[mi][nt], al[mi][0], al[mi][1], al[mi][2], al[mi][3], bh0, bh1);
                }
            }
        }
        __syncthreads();
    }

    // epilogue: bias + store
#pragma unroll
    for (int nt = 0; nt < 8; nt++) {
        int c0 = n0 + brow + nt * 8 + tg * 2;
        float2 bb = *(const float2*)&bias[c0];
#pragma unroll
        for (int mi = 0; mi < 2; mi++) {
            int r0 = m0 + arow + mi * 16 + g;
            *(float2*)&C[(size_t)r0 * N + c0] =
                make_float2(acc[mi][nt][0] + bb.x, acc[mi][nt][1] + bb.y);
            *(float2*)&C[(size_t)(r0 + 8) * N + c0] =
                make_float2(acc[mi][nt][2] + bb.x, acc[mi][nt][3] + bb.y);
        }
    }
}

// ---------------------------------------------------------------------------
// Tensor-core flash attention (tf32 mma.sync.m16n8k8).  (unchanged from R2)
// ---------------------------------------------------------------------------
#define QK_STR 260
#define V_STR  264
#define P_STR  68
#define ATTN_SMEM_FLOATS (2 * 64 * QK_STR + 64 * V_STR + 64 * P_STR + 192)
#define ATTN_SMEM_BYTES  (ATTN_SMEM_FLOATS * 4)

__global__ __launch_bounds__(256) void attn_tc_kernel(
    const float* __restrict__ Q, const float* __restrict__ K,
    const float* __restrict__ V, float* __restrict__ O)
{
    extern __shared__ float sm[];
    float* Qs   = sm;                      // 64 x 260
    float* Ks   = Qs + 64 * QK_STR;        // 64 x 260
    float* Vs   = Ks + 64 * QK_STR;        // 64 x 264
    float* Ps   = Vs + 64 * V_STR;         // 64 x 68
    float* sm_m = Ps + 64 * P_STR;         // 64
    float* sm_l = sm_m + 64;               // 64
    float* sm_a = sm_l + 64;               // 64

    const int tid  = threadIdx.x;
    const int lane = tid & 31;
    const int w    = tid >> 5;
    const int g    = lane >> 2;   // 0..7
    const int tg   = lane & 3;    // 0..3
    const int wr   = w >> 1;      // 0..3
    const int wc   = w & 1;       // 0..1

    const int bh = blockIdx.y;
    const int b  = bh / H_DIM;
    const int h  = bh % H_DIM;
    const int t0 = blockIdx.x * 64;
    const size_t head = (size_t)b * F_DIM + (size_t)h * DH;

    if (tid < 64) { sm_m[tid] = -1e30f; sm_l[tid] = 0.f; }

#pragma unroll
    for (int i = 0; i < 16; i++) {
        int idx = tid + i * 256;
        int r = idx >> 6, c = idx & 63;
        float4 v = *(const float4*)&Q[(size_t)(t0 + r) * ROW_STRIDE + head + c * 4];
        v.x = to_tf32(v.x); v.y = to_tf32(v.y);
        v.z = to_tf32(v.z); v.w = to_tf32(v.w);
        *(float4*)&Qs[r * QK_STR + c * 4] = v;
    }

    float oacc[16][4];
#pragma unroll
    for (int nt = 0; nt < 16; nt++)
#pragma unroll
        for (int j = 0; j < 4; j++) oacc[nt][j] = 0.f;

    const int rq = wr * 16, ck = wc * 32;   // S tile origin
    const int ro = wr * 16, co = wc * 128;  // O tile origin

    for (int s0 = 0; s0 < T_DIM; s0 += 64) {
        __syncthreads();

#pragma unroll
        for (int i = 0; i < 16; i++) {
            int idx = tid + i * 256;
            int r = idx >> 6, c = idx & 63;
            size_t gaddr = (size_t)(s0 + r) * ROW_STRIDE + head + c * 4;
            float4 kk = *(const float4*)&K[gaddr];
            kk.x = to_tf32(kk.x); kk.y = to_tf32(kk.y);
            kk.z = to_tf32(kk.z); kk.w = to_tf32(kk.w);
            *(float4*)&Ks[r * QK_STR + c * 4] = kk;
            float4 vv = *(const float4*)&V[gaddr];
            vv.x = to_tf32(vv.x); vv.y = to_tf32(vv.y);
            vv.z = to_tf32(vv.z); vv.w = to_tf32(vv.w);
            *(float4*)&Vs[r * V_STR + c * 4] = vv;
        }
        __syncthreads();

        float sacc[4][4];
#pragma unroll
        for (int nt = 0; nt < 4; nt++)
#pragma unroll
            for (int j = 0; j < 4; j++) sacc[nt][j] = 0.f;

#pragma unroll 8
        for (int k0 = 0; k0 < DH; k0 += 8) {
            uint32_t a0 = __float_as_uint(Qs[(rq + g)     * QK_STR + k0 + tg]);
            uint32_t a1 = __float_as_uint(Qs[(rq + g + 8) * QK_STR + k0 + tg]);
            uint32_t a2 = __float_as_uint(Qs[(rq + g)     * QK_STR + k0 + tg + 4]);
            uint32_t a3 = __float_as_uint(Qs[(rq + g + 8) * QK_STR + k0 + tg + 4]);
#pragma unroll
            for (int nt = 0; nt < 4; nt++) {
                int n0 = ck + nt * 8;
                uint32_t b0 = __float_as_uint(Ks[(n0 + g) * QK_STR + k0 + tg]);
                uint32_t b1 = __float_as_uint(Ks[(n0 + g) * QK_STR + k0 + tg + 4]);
                mma8(sacc[nt], a0, a1, a2, a3, b0, b1);
            }
        }

#pragma unroll
        for (int nt = 0; nt < 4; nt++) {
            int c0 = ck + nt * 8 + tg * 2;
            *(float2*)&Ps[(rq + g)     * P_STR + c0] = make_float2(sacc[nt][0], sacc[nt][1]);
            *(float2*)&Ps[(rq + g + 8) * P_STR + c0] = make_float2(sacc[nt][2], sacc[nt][3]);
        }
        __syncthreads();

        {
            int r = tid >> 2, qd = tid & 3;
            float* row = &Ps[r * P_STR + qd * 16];
            float4 v0 = *(float4*)&row[0];
            float4 v1 = *(float4*)&row[4];
            float4 v2 = *(float4*)&row[8];
            float4 v3 = *(float4*)&row[12];
            const float sc = 0.125f;
            v0.x *= sc; v0.y *= sc; v0.z *= sc; v0.w *= sc;
            v1.x *= sc; v1.y *= sc; v1.z *= sc; v1.w *= sc;
            v2.x *= sc; v2.y *= sc; v2.z *= sc; v2.w *= sc;
            v3.x *= sc; v3.y *= sc; v3.z *= sc; v3.w *= sc;

            float mx = fmaxf(fmaxf(fmaxf(v0.x, v0.y), fmaxf(v0.z, v0.w)),
                             fmaxf(fmaxf(v1.x, v1.y), fmaxf(v1.z, v1.w)));
            mx = fmaxf(mx, fmaxf(fmaxf(fmaxf(v2.x, v2.y), fmaxf(v2.z, v2.w)),
                                 fmaxf(fmaxf(v3.x, v3.y), fmaxf(v3.z, v3.w))));
            mx = fmaxf(mx, __shfl_xor_sync(0xffffffffu, mx, 1));
            mx = fmaxf(mx, __shfl_xor_sync(0xffffffffu, mx, 2));

            float m_old = sm_m[r];
            float m_new = fmaxf(m_old, mx);
            float alpha = __expf(m_old - m_new);

            v0.x = __expf(v0.x - m_new); v0.y = __expf(v0.y - m_new);
            v0.z = __expf(v0.z - m_new); v0.w = __expf(v0.w - m_new);
            v1.x = __expf(v1.x - m_new); v1.y = __expf(v1.y - m_new);
            v1.z = __expf(v1.z - m_new); v1.w = __expf(v1.w - m_new);
            v2.x = __expf(v2.x - m_new); v2.y = __expf(v2.y - m_new);
            v2.z = __expf(v2.z - m_new); v2.w = __expf(v2.w - m_new);
            v3.x = __expf(v3.x - m_new); v3.y = __expf(v3.y - m_new);
            v3.z = __expf(v3.z - m_new); v3.w = __expf(v3.w - m_new);

            float s = (v0.x + v0.y + v0.z + v0.w) + (v1.x + v1.y + v1.z + v1.w)
                    + (v2.x + v2.y + v2.z + v2.w) + (v3.x + v3.y + v3.z + v3.w);
            s += __shfl_xor_sync(0xffffffffu, s, 1);
            s += __shfl_xor_sync(0xffffffffu, s, 2);

            v0.x = to_tf32(v0.x); v0.y = to_tf32(v0.y); v0.z = to_tf32(v0.z); v0.w = to_tf32(v0.w);
            v1.x = to_tf32(v1.x); v1.y = to_tf32(v1.y); v1.z = to_tf32(v1.z); v1.w = to_tf32(v1.w);
            v2.x = to_tf32(v2.x); v2.y = to_tf32(v2.y); v2.z = to_tf32(v2.z); v2.w = to_tf32(v2.w);
            v3.x = to_tf32(v3.x); v3.y = to_tf32(v3.y); v3.z = to_tf32(v3.z); v3.w = to_tf32(v3.w);
            *(float4*)&row[0]  = v0;
            *(float4*)&row[4]  = v1;
            *(float4*)&row[8]  = v2;
            *(float4*)&row[12] = v3;

            if (qd == 0) {
                sm_m[r] = m_new;
                sm_l[r] = sm_l[r] * alpha + s;
                sm_a[r] = alpha;
            }
        }
        __syncthreads();

        {
            float al0 = sm_a[ro + g];
            float al1 = sm_a[ro + g + 8];
#pragma unroll
            for (int nt = 0; nt < 16; nt++) {
                oacc[nt][0] *= al0; oacc[nt][1] *= al0;
                oacc[nt][2] *= al1; oacc[nt][3] *= al1;
            }
        }
#pragma unroll
        for (int k0 = 0; k0 < 64; k0 += 8) {
            uint32_t a0 = __float_as_uint(Ps[(ro + g)     * P_STR + k0 + tg]);
            uint32_t a1 = __float_as_uint(Ps[(ro + g + 8) * P_STR + k0 + tg]);
            uint32_t a2 = __float_as_uint(Ps[(ro + g)     * P_STR + k0 + tg + 4]);
            uint32_t a3 = __float_as_uint(Ps[(ro + g + 8) * P_STR + k0 + tg + 4]);
#pragma unroll
            for (int nt = 0; nt < 16; nt++) {
                int n0 = co + nt * 8;
                uint32_t b0 = __float_as_uint(Vs[(k0 + tg)     * V_STR + n0 + g]);
                uint32_t b1 = __float_as_uint(Vs[(k0 + tg + 4) * V_STR + n0 + g]);
                mma8(oacc[nt], a0, a1, a2, a3, b0, b1);
            }
        }
    }

    {
        float il0 = 1.f / sm_l[ro + g];
        float il1 = 1.f / sm_l[ro + g + 8];
        size_t r0 = (size_t)(t0 + ro + g)     * ROW_STRIDE + head + co;
        size_t r1 = (size_t)(t0 + ro + g + 8) * ROW_STRIDE + head + co;
#pragma unroll
        for (int nt = 0; nt < 16; nt++) {
            int c0 = nt * 8 + tg * 2;
            *(float2*)&O[r0 + c0] = make_float2(oacc[nt][0] * il0, oacc[nt][1] * il0);
            *(float2*)&O[r1 + c0] = make_float2(oacc[nt][2] * il1, oacc[nt][3] * il1);
        }
    }
}

// ---------------------------------------------------------------------------
extern "C" void kernel_launch(void* const* d_in, const int* in_sizes, int n_in,
                              void* d_out, int out_size)
{
    const float* x  = (const float*)d_in[0];
    const float* Wq = (const float*)d_in[1];
    const float* bq = (const float*)d_in[2];
    const float* Wk = (const float*)d_in[3];
    const float* bk = (const float*)d_in[4];
    const float* Wv = (const float*)d_in[5];
    const float* bv = (const float*)d_in[6];
    const float* Wo = (const float*)d_in[7];
    const float* bo = (const float*)d_in[8];
    float* out = (float*)d_out;

    float *Qp, *Kp, *Vp, *Op;
    cudaGetSymbolAddress((void**)&Qp, g_Q);
    cudaGetSymbolAddress((void**)&Kp, g_K);
    cudaGetSymbolAddress((void**)&Vp, g_V);
    cudaGetSymbolAddress((void**)&Op, g_O);

    dim3 ggrid(F_DIM / 128, M_ROWS / 128);   // (6, 128)

    gemm_tc_kernel<<<ggrid, 256>>>(x, Wq, bq, Qp, M_ROWS, F_DIM, F_DIM);
    gemm_tc_kernel<<<ggrid, 256>>>(x, Wk, bk, Kp, M_ROWS, F_DIM, F_DIM);
    gemm_tc_kernel<<<ggrid, 256>>>(x, Wv, bv, Vp, M_ROWS, F_DIM, F_DIM);

    cudaFuncSetAttribute(attn_tc_kernel,
                         cudaFuncAttributeMaxDynamicSharedMemorySize,
                         ATTN_SMEM_BYTES);
    attn_tc_kernel<<<dim3(T_DIM / 64, B_DIM * H_DIM), 256, ATTN_SMEM_BYTES>>>(
        Qp, Kp, Vp, Op);

    gemm_tc_kernel<<<ggrid, 256>>>(Op, Wo, bo, out, M_ROWS, F_DIM, F_DIM);
}

// round 4
// speedup vs baseline: 4.6432x; 1.3280x over previous
#include <cuda_runtime.h>
#include <cuda_bf16.h>
#include <math.h>
#include <stdint.h>

// Problem constants
#define T_DIM 2048
#define B_DIM 8
#define F_DIM 768
#define H_DIM 3
#define DH    256
#define M_ROWS (T_DIM * B_DIM)   // 16384
#define ROW_STRIDE 6144          // B_DIM * F_DIM

// Scratch (allocation-free: device globals)
__device__ float g_Q[T_DIM * B_DIM * F_DIM];
__device__ float g_K[T_DIM * B_DIM * F_DIM];
__device__ float g_V[T_DIM * B_DIM * F_DIM];
__device__ float g_O[T_DIM * B_DIM * F_DIM];

// ---------------------------------------------------------------------------
// helpers
// ---------------------------------------------------------------------------
__device__ __forceinline__ float to_tf32(float x) {
    uint32_t u;
    asm("cvt.rna.tf32.f32 %0, %1;" : "=r"(u) : "f"(x));
    return __uint_as_float(u);
}

__device__ __forceinline__ void mma8(float c[4],
                                     uint32_t a0, uint32_t a1, uint32_t a2, uint32_t a3,
                                     uint32_t b0, uint32_t b1) {
    asm volatile(
        "mma.sync.aligned.m16n8k8.row.col.f32.tf32.tf32.f32 "
        "{%0,%1,%2,%3}, {%4,%5,%6,%7}, {%8,%9}, {%0,%1,%2,%3};"
        : "+f"(c[0]), "+f"(c[1]), "+f"(c[2]), "+f"(c[3])
        : "r"(a0), "r"(a1), "r"(a2), "r"(a3), "r"(b0), "r"(b1));
}

__device__ __forceinline__ void mma16(float c[4], const uint32_t a[4],
                                      uint32_t b0, uint32_t b1) {
    asm volatile(
        "mma.sync.aligned.m16n8k16.row.col.f32.bf16.bf16.f32 "
        "{%0,%1,%2,%3}, {%4,%5,%6,%7}, {%8,%9}, {%0,%1,%2,%3};"
        : "+f"(c[0]), "+f"(c[1]), "+f"(c[2]), "+f"(c[3])
        : "r"(a[0]), "r"(a[1]), "r"(a[2]), "r"(a[3]), "r"(b0), "r"(b1));
}

#define LDSM_X4(R, addr)                                                    \
    asm volatile("ldmatrix.sync.aligned.m8n8.x4.shared.b16 "                \
                 "{%0,%1,%2,%3}, [%4];"                                     \
                 : "=r"((R)[0]), "=r"((R)[1]), "=r"((R)[2]), "=r"((R)[3])   \
                 : "r"(addr))

// split fp32x4 into bf16 hi/lo and store (4 contiguous elems)
__device__ __forceinline__ void split4(__nv_bfloat16* hp, __nv_bfloat16* lp, float4 v) {
    __nv_bfloat16 h0 = __float2bfloat16(v.x);
    __nv_bfloat16 h1 = __float2bfloat16(v.y);
    __nv_bfloat16 h2 = __float2bfloat16(v.z);
    __nv_bfloat16 h3 = __float2bfloat16(v.w);
    __nv_bfloat162 hh0; hh0.x = h0; hh0.y = h1;
    __nv_bfloat162 hh1; hh1.x = h2; hh1.y = h3;
    *(__nv_bfloat162*)hp       = hh0;
    *((__nv_bfloat162*)hp + 1) = hh1;
    __nv_bfloat162 ll0, ll1;
    ll0.x = __float2bfloat16(v.x - __bfloat162float(h0));
    ll0.y = __float2bfloat16(v.y - __bfloat162float(h1));
    ll1.x = __float2bfloat16(v.z - __bfloat162float(h2));
    ll1.y = __float2bfloat16(v.w - __bfloat162float(h3));
    *(__nv_bfloat162*)lp       = ll0;
    *((__nv_bfloat162*)lp + 1) = ll1;
}

// ---------------------------------------------------------------------------
// bf16-split tensor-core GEMM: C[m,n] = sum_k A[m,k]*W[n,k] + bias[n]
// BM=128, BN=128, BK=16, 256 threads (8 warps 4x2), warp tile 32x64.
// A=Ah+Al, W=Wh+Wl (bf16): C ≈ AhWh + AhWl + AlWh via mma.m16n8k16.
// smem bf16 stride 24 (48B) -> ldmatrix conflict-free. Double-buffered.
// ---------------------------------------------------------------------------
#define GTILE (128 * 24)   // bf16 elems per tile

__global__ __launch_bounds__(256, 2) void gemm_bf16s_kernel(
    const float* __restrict__ A, const float* __restrict__ W,
    const float* __restrict__ bias, float* __restrict__ C,
    int M, int N, int K)
{
    __shared__ __nv_bfloat16 smem[2][4][GTILE];  // [stage][Ah,Al,Bh,Bl]

    const int tid  = threadIdx.x;
    const int lane = tid & 31;
    const int w    = tid >> 5;
    const int g    = lane >> 2;
    const int tg   = lane & 3;
    const int wr   = w >> 1;       // 0..3 (m)
    const int wc   = w & 1;        // 0..1 (n)

    const int m0 = blockIdx.y * 128;
    const int n0 = blockIdx.x * 128;

    const int lrow0 = tid >> 2;          // 0..63
    const int lrow1 = lrow0 + 64;        // 64..127
    const int col4  = tid & 3;           // float4 index (4 elems each)

    const uint32_t smem_u32 = (uint32_t)__cvta_generic_to_shared(&smem[0][0][0]);

    float4 pa0, pa1, pw0, pw1;
    pa0 = *(const float4*)&A[(size_t)(m0 + lrow0) * K + col4 * 4];
    pa1 = *(const float4*)&A[(size_t)(m0 + lrow1) * K + col4 * 4];
    pw0 = *(const float4*)&W[(size_t)(n0 + lrow0) * K + col4 * 4];
    pw1 = *(const float4*)&W[(size_t)(n0 + lrow1) * K + col4 * 4];

    float acc[2][8][4];
#pragma unroll
    for (int mi = 0; mi < 2; mi++)
#pragma unroll
        for (int nt = 0; nt < 8; nt++)
#pragma unroll
            for (int j = 0; j < 4; j++) acc[mi][nt][j] = 0.f;

    const int arow = wr * 32;
    const int brow = wc * 64;

    // fragment smem byte offsets (within one tile) — constant per thread
    const uint32_t a_off0 = ((arow + (lane & 15)) * 24 + ((lane >> 4) << 3)) * 2;
    const uint32_t a_off1 = a_off0 + 16 * 24 * 2;
    const uint32_t b_off  = ((brow + ((lane >> 4) << 3) + (lane & 7)) * 24
                             + (((lane >> 3) & 1) << 3)) * 2;

    // prologue: store stage 0
    {
        __nv_bfloat16* Ah = &smem[0][0][0];
        __nv_bfloat16* Al = &smem[0][1][0];
        __nv_bfloat16* Bh = &smem[0][2][0];
        __nv_bfloat16* Bl = &smem[0][3][0];
        split4(&Ah[lrow0 * 24 + col4 * 4], &Al[lrow0 * 24 + col4 * 4], pa0);
        split4(&Ah[lrow1 * 24 + col4 * 4], &Al[lrow1 * 24 + col4 * 4], pa1);
        split4(&Bh[lrow0 * 24 + col4 * 4], &Bl[lrow0 * 24 + col4 * 4], pw0);
        split4(&Bh[lrow1 * 24 + col4 * 4], &Bl[lrow1 * 24 + col4 * 4], pw1);
    }
    __syncthreads();

    const int nIter = K / 16;   // 48
    for (int it = 0; it < nIter; ++it) {
        const int cur = it & 1;
        const bool hasNext = (it + 1 < nIter);
        if (hasNext) {
            int kc = (it + 1) * 16 + col4 * 4;
            pa0 = *(const float4*)&A[(size_t)(m0 + lrow0) * K + kc];
            pa1 = *(const float4*)&A[(size_t)(m0 + lrow1) * K + kc];
            pw0 = *(const float4*)&W[(size_t)(n0 + lrow0) * K + kc];
            pw1 = *(const float4*)&W[(size_t)(n0 + lrow1) * K + kc];
        }

        // ---- compute on stage cur ----
        {
            const uint32_t sAh = smem_u32 + (cur * 4 + 0) * (GTILE * 2);
            const uint32_t sAl = smem_u32 + (cur * 4 + 1) * (GTILE * 2);
            const uint32_t sBh = smem_u32 + (cur * 4 + 2) * (GTILE * 2);
            const uint32_t sBl = smem_u32 + (cur * 4 + 3) * (GTILE * 2);

            uint32_t ah[2][4], al[2][4];
            LDSM_X4(ah[0], sAh + a_off0);
            LDSM_X4(ah[1], sAh + a_off1);
            LDSM_X4(al[0], sAl + a_off0);
            LDSM_X4(al[1], sAl + a_off1);

#pragma unroll
            for (int p = 0; p < 4; p++) {
                uint32_t bh[4], bl[4];
                LDSM_X4(bh, sBh + b_off + p * (16 * 24 * 2));
                LDSM_X4(bl, sBl + b_off + p * (16 * 24 * 2));
#pragma unroll
                for (int j = 0; j < 2; j++) {
                    const int nt = p * 2 + j;
#pragma unroll
                    for (int mi = 0; mi < 2; mi++) {
                        mma16(acc[mi][nt], ah[mi], bh[2 * j], bh[2 * j + 1]);
                        mma16(acc[mi][nt], ah[mi], bl[2 * j], bl[2 * j + 1]);
                        mma16(acc[mi][nt], al[mi], bh[2 * j], bh[2 * j + 1]);
                    }
                }
            }
        }

        if (hasNext) {
            const int nxt = cur ^ 1;
            __nv_bfloat16* Ah = &smem[nxt][0][0];
            __nv_bfloat16* Al = &smem[nxt][1][0];
            __nv_bfloat16* Bh = &smem[nxt][2][0];
            __nv_bfloat16* Bl = &smem[nxt][3][0];
            split4(&Ah[lrow0 * 24 + col4 * 4], &Al[lrow0 * 24 + col4 * 4], pa0);
            split4(&Ah[lrow1 * 24 + col4 * 4], &Al[lrow1 * 24 + col4 * 4], pa1);
            split4(&Bh[lrow0 * 24 + col4 * 4], &Bl[lrow0 * 24 + col4 * 4], pw0);
            split4(&Bh[lrow1 * 24 + col4 * 4], &Bl[lrow1 * 24 + col4 * 4], pw1);
            __syncthreads();
        }
    }

    // epilogue: bias + store
#pragma unroll
    for (int nt = 0; nt < 8; nt++) {
        int c0 = n0 + brow + nt * 8 + tg * 2;
        float2 bb = *(const float2*)&bias[c0];
#pragma unroll
        for (int mi = 0; mi < 2; mi++) {
            int r0 = m0 + arow + mi * 16 + g;
            *(float2*)&C[(size_t)r0 * N + c0] =
                make_float2(acc[mi][nt][0] + bb.x, acc[mi][nt][1] + bb.y);
            *(float2*)&C[(size_t)(r0 + 8) * N + c0] =
                make_float2(acc[mi][nt][2] + bb.x, acc[mi][nt][3] + bb.y);
        }
    }
}

// ---------------------------------------------------------------------------
// Tensor-core flash attention (tf32 mma.sync.m16n8k8).  (unchanged)
// ---------------------------------------------------------------------------
#define QK_STR 260
#define V_STR  264
#define P_STR  68
#define ATTN_SMEM_FLOATS (2 * 64 * QK_STR + 64 * V_STR + 64 * P_STR + 192)
#define ATTN_SMEM_BYTES  (ATTN_SMEM_FLOATS * 4)

__global__ __launch_bounds__(256) void attn_tc_kernel(
    const float* __restrict__ Q, const float* __restrict__ K,
    const float* __restrict__ V, float* __restrict__ O)
{
    extern __shared__ float sm[];
    float* Qs   = sm;                      // 64 x 260
    float* Ks   = Qs + 64 * QK_STR;        // 64 x 260
    float* Vs   = Ks + 64 * QK_STR;        // 64 x 264
    float* Ps   = Vs + 64 * V_STR;         // 64 x 68
    float* sm_m = Ps + 64 * P_STR;         // 64
    float* sm_l = sm_m + 64;               // 64
    float* sm_a = sm_l + 64;               // 64

    const int tid  = threadIdx.x;
    const int lane = tid & 31;
    const int w    = tid >> 5;
    const int g    = lane >> 2;
    const int tg   = lane & 3;
    const int wr   = w >> 1;
    const int wc   = w & 1;

    const int bh = blockIdx.y;
    const int b  = bh / H_DIM;
    const int h  = bh % H_DIM;
    const int t0 = blockIdx.x * 64;
    const size_t head = (size_t)b * F_DIM + (size_t)h * DH;

    if (tid < 64) { sm_m[tid] = -1e30f; sm_l[tid] = 0.f; }

#pragma unroll
    for (int i = 0; i < 16; i++) {
        int idx = tid + i * 256;
        int r = idx >> 6, c = idx & 63;
        float4 v = *(const float4*)&Q[(size_t)(t0 + r) * ROW_STRIDE + head + c * 4];
        v.x = to_tf32(v.x); v.y = to_tf32(v.y);
        v.z = to_tf32(v.z); v.w = to_tf32(v.w);
        *(float4*)&Qs[r * QK_STR + c * 4] = v;
    }

    float oacc[16][4];
#pragma unroll
    for (int nt = 0; nt < 16; nt++)
#pragma unroll
        for (int j = 0; j < 4; j++) oacc[nt][j] = 0.f;

    const int rq = wr * 16, ck = wc * 32;
    const int ro = wr * 16, co = wc * 128;

    for (int s0 = 0; s0 < T_DIM; s0 += 64) {
        __syncthreads();

#pragma unroll
        for (int i = 0; i < 16; i++) {
            int idx = tid + i * 256;
            int r = idx >> 6, c = idx & 63;
            size_t gaddr = (size_t)(s0 + r) * ROW_STRIDE + head + c * 4;
            float4 kk = *(const float4*)&K[gaddr];
            kk.x = to_tf32(kk.x); kk.y = to_tf32(kk.y);
            kk.z = to_tf32(kk.z); kk.w = to_tf32(kk.w);
            *(float4*)&Ks[r * QK_STR + c * 4] = kk;
            float4 vv = *(const float4*)&V[gaddr];
            vv.x = to_tf32(vv.x); vv.y = to_tf32(vv.y);
            vv.z = to_tf32(vv.z); vv.w = to_tf32(vv.w);
            *(float4*)&Vs[r * V_STR + c * 4] = vv;
        }
        __syncthreads();

        float sacc[4][4];
#pragma unroll
        for (int nt = 0; nt < 4; nt++)
#pragma unroll
            for (int j = 0; j < 4; j++) sacc[nt][j] = 0.f;

#pragma unroll 8
        for (int k0 = 0; k0 < DH; k0 += 8) {
            uint32_t a0 = __float_as_uint(Qs[(rq + g)     * QK_STR + k0 + tg]);
            uint32_t a1 = __float_as_uint(Qs[(rq + g + 8) * QK_STR + k0 + tg]);
            uint32_t a2 = __float_as_uint(Qs[(rq + g)     * QK_STR + k0 + tg + 4]);
            uint32_t a3 = __float_as_uint(Qs[(rq + g + 8) * QK_STR + k0 + tg + 4]);
#pragma unroll
            for (int nt = 0; nt < 4; nt++) {
                int n0 = ck + nt * 8;
                uint32_t b0 = __float_as_uint(Ks[(n0 + g) * QK_STR + k0 + tg]);
                uint32_t b1 = __float_as_uint(Ks[(n0 + g) * QK_STR + k0 + tg + 4]);
                mma8(sacc[nt], a0, a1, a2, a3, b0, b1);
            }
        }

#pragma unroll
        for (int nt = 0; nt < 4; nt++) {
            int c0 = ck + nt * 8 + tg * 2;
            *(float2*)&Ps[(rq + g)     * P_STR + c0] = make_float2(sacc[nt][0], sacc[nt][1]);
            *(float2*)&Ps[(rq + g + 8) * P_STR + c0] = make_float2(sacc[nt][2], sacc[nt][3]);
        }
        __syncthreads();

        {
            int r = tid >> 2, qd = tid & 3;
            float* row = &Ps[r * P_STR + qd * 16];
            float4 v0 = *(float4*)&row[0];
            float4 v1 = *(float4*)&row[4];
            float4 v2 = *(float4*)&row[8];
            float4 v3 = *(float4*)&row[12];
            const float sc = 0.125f;
            v0.x *= sc; v0.y *= sc; v0.z *= sc; v0.w *= sc;
            v1.x *= sc; v1.y *= sc; v1.z *= sc; v1.w *= sc;
            v2.x *= sc; v2.y *= sc; v2.z *= sc; v2.w *= sc;
            v3.x *= sc; v3.y *= sc; v3.z *= sc; v3.w *= sc;

            float mx = fmaxf(fmaxf(fmaxf(v0.x, v0.y), fmaxf(v0.z, v0.w)),
                             fmaxf(fmaxf(v1.x, v1.y), fmaxf(v1.z, v1.w)));
            mx = fmaxf(mx, fmaxf(fmaxf(fmaxf(v2.x, v2.y), fmaxf(v2.z, v2.w)),
                                 fmaxf(fmaxf(v3.x, v3.y), fmaxf(v3.z, v3.w))));
            mx = fmaxf(mx, __shfl_xor_sync(0xffffffffu, mx, 1));
            mx = fmaxf(mx, __shfl_xor_sync(0xffffffffu, mx, 2));

            float m_old = sm_m[r];
            float m_new = fmaxf(m_old, mx);
            float alpha = __expf(m_old - m_new);

            v0.x = __expf(v0.x - m_new); v0.y = __expf(v0.y - m_new);
            v0.z = __expf(v0.z - m_new); v0.w = __expf(v0.w - m_new);
            v1.x = __expf(v1.x - m_new); v1.y = __expf(v1.y - m_new);
            v1.z = __expf(v1.z - m_new); v1.w = __expf(v1.w - m_new);
            v2.x = __expf(v2.x - m_new); v2.y = __expf(v2.y - m_new);
            v2.z = __expf(v2.z - m_new); v2.w = __expf(v2.w - m_new);
            v3.x = __expf(v3.x - m_new); v3.y = __expf(v3.y - m_new);
            v3.z = __expf(v3.w - m_new) * 0.f + __expf(v3.z - m_new); v3.w = __expf(v3.w - m_new);

            float s = (v0.x + v0.y + v0.z + v0.w) + (v1.x + v1.y + v1.z + v1.w)
                    + (v2.x + v2.y + v2.z + v2.w) + (v3.x + v3.y + v3.z + v3.w);
            s += __shfl_xor_sync(0xffffffffu, s, 1);
            s += __shfl_xor_sync(0xffffffffu, s, 2);

            v0.x = to_tf32(v0.x); v0.y = to_tf32(v0.y); v0.z = to_tf32(v0.z); v0.w = to_tf32(v0.w);
            v1.x = to_tf32(v1.x); v1.y = to_tf32(v1.y); v1.z = to_tf32(v1.z); v1.w = to_tf32(v1.w);
            v2.x = to_tf32(v2.x); v2.y = to_tf32(v2.y); v2.z = to_tf32(v2.z); v2.w = to_tf32(v2.w);
            v3.x = to_tf32(v3.x); v3.y = to_tf32(v3.y); v3.z = to_tf32(v3.z); v3.w = to_tf32(v3.w);
            *(float4*)&row[0]  = v0;
            *(float4*)&row[4]  = v1;
            *(float4*)&row[8]  = v2;
            *(float4*)&row[12] = v3;

            if (qd == 0) {
                sm_m[r] = m_new;
                sm_l[r] = sm_l[r] * alpha + s;
                sm_a[r] = alpha;
            }
        }
        __syncthreads();

        {
            float al0 = sm_a[ro + g];
            float al1 = sm_a[ro + g + 8];
#pragma unroll
            for (int nt = 0; nt < 16; nt++) {
                oacc[nt][0] *= al0; oacc[nt][1] *= al0;
                oacc[nt][2] *= al1; oacc[nt][3] *= al1;
            }
        }
#pragma unroll
        for (int k0 = 0; k0 < 64; k0 += 8) {
            uint32_t a0 = __float_as_uint(Ps[(ro + g)     * P_STR + k0 + tg]);
            uint32_t a1 = __float_as_uint(Ps[(ro + g + 8) * P_STR + k0 + tg]);
            uint32_t a2 = __float_as_uint(Ps[(ro + g)     * P_STR + k0 + tg + 4]);
            uint32_t a3 = __float_as_uint(Ps[(ro + g + 8) * P_STR + k0 + tg + 4]);
#pragma unroll
            for (int nt = 0; nt < 16; nt++) {
                int n0 = co + nt * 8;
                uint32_t b0 = __float_as_uint(Vs[(k0 + tg)     * V_STR + n0 + g]);
                uint32_t b1 = __float_as_uint(Vs[(k0 + tg + 4) * V_STR + n0 + g]);
                mma8(oacc[nt], a0, a1, a2, a3, b0, b1);
            }
        }
    }

    {
        float il0 = 1.f / sm_l[ro + g];
        float il1 = 1.f / sm_l[ro + g + 8];
        size_t r0 = (size_t)(t0 + ro + g)     * ROW_STRIDE + head + co;
        size_t r1 = (size_t)(t0 + ro + g + 8) * ROW_STRIDE + head + co;
#pragma unroll
        for (int nt = 0; nt < 16; nt++) {
            int c0 = nt * 8 + tg * 2;
            *(float2*)&O[r0 + c0] = make_float2(oacc[nt][0] * il0, oacc[nt][1] * il0);
            *(float2*)&O[r1 + c0] = make_float2(oacc[nt][2] * il1, oacc[nt][3] * il1);
        }
    }
}

// ---------------------------------------------------------------------------
extern "C" void kernel_launch(void* const* d_in, const int* in_sizes, int n_in,
                              void* d_out, int out_size)
{
    const float* x  = (const float*)d_in[0];
    const float* Wq = (const float*)d_in[1];
    const float* bq = (const float*)d_in[2];
    const float* Wk = (const float*)d_in[3];
    const float* bk = (const float*)d_in[4];
    const float* Wv = (const float*)d_in[5];
    const float* bv = (const float*)d_in[6];
    const float* Wo = (const float*)d_in[7];
    const float* bo = (const float*)d_in[8];
    float* out = (float*)d_out;

    float *Qp, *Kp, *Vp, *Op;
    cudaGetSymbolAddress((void**)&Qp, g_Q);
    cudaGetSymbolAddress((void**)&Kp, g_K);
    cudaGetSymbolAddress((void**)&Vp, g_V);
    cudaGetSymbolAddress((void**)&Op, g_O);

    dim3 ggrid(F_DIM / 128, M_ROWS / 128);   // (6, 128)

    gemm_bf16s_kernel<<<ggrid, 256>>>(x, Wq, bq, Qp, M_ROWS, F_DIM, F_DIM);
    gemm_bf16s_kernel<<<ggrid, 256>>>(x, Wk, bk, Kp, M_ROWS, F_DIM, F_DIM);
    gemm_bf16s_kernel<<<ggrid, 256>>>(x, Wv, bv, Vp, M_ROWS, F_DIM, F_DIM);

    cudaFuncSetAttribute(attn_tc_kernel,
                         cudaFuncAttributeMaxDynamicSharedMemorySize,
                         ATTN_SMEM_BYTES);
    attn_tc_kernel<<<dim3(T_DIM / 64, B_DIM * H_DIM), 256, ATTN_SMEM_BYTES>>>(
        Qp, Kp, Vp, Op);

    gemm_bf16s_kernel<<<ggrid, 256>>>(Op, Wo, bo, out, M_ROWS, F_DIM, F_DIM);
}

// round 5
// speedup vs baseline: 5.8801x; 1.2664x over previous
#include <cuda_runtime.h>
#include <cuda_bf16.h>
#include <math.h>
#include <stdint.h>

// Problem constants
#define T_DIM 2048
#define B_DIM 8
#define F_DIM 768
#define H_DIM 3
#define DH    256
#define M_ROWS (T_DIM * B_DIM)   // 16384
#define ROW_STRIDE 6144          // B_DIM * F_DIM

// Scratch (allocation-free: device globals)
__device__ float g_Q[T_DIM * B_DIM * F_DIM];
__device__ float g_K[T_DIM * B_DIM * F_DIM];
__device__ float g_V[T_DIM * B_DIM * F_DIM];
__device__ float g_O[T_DIM * B_DIM * F_DIM];

// ---------------------------------------------------------------------------
// helpers
// ---------------------------------------------------------------------------
__device__ __forceinline__ float to_tf32(float x) {
    uint32_t u;
    asm("cvt.rna.tf32.f32 %0, %1;" : "=r"(u) : "f"(x));
    return __uint_as_float(u);
}

__device__ __forceinline__ void mma8(float c[4],
                                     uint32_t a0, uint32_t a1, uint32_t a2, uint32_t a3,
                                     uint32_t b0, uint32_t b1) {
    asm volatile(
        "mma.sync.aligned.m16n8k8.row.col.f32.tf32.tf32.f32 "
        "{%0,%1,%2,%3}, {%4,%5,%6,%7}, {%8,%9}, {%0,%1,%2,%3};"
        : "+f"(c[0]), "+f"(c[1]), "+f"(c[2]), "+f"(c[3])
        : "r"(a0), "r"(a1), "r"(a2), "r"(a3), "r"(b0), "r"(b1));
}

__device__ __forceinline__ void mma16(float c[4], const uint32_t a[4],
                                      uint32_t b0, uint32_t b1) {
    asm volatile(
        "mma.sync.aligned.m16n8k16.row.col.f32.bf16.bf16.f32 "
        "{%0,%1,%2,%3}, {%4,%5,%6,%7}, {%8,%9}, {%0,%1,%2,%3};"
        : "+f"(c[0]), "+f"(c[1]), "+f"(c[2]), "+f"(c[3])
        : "r"(a[0]), "r"(a[1]), "r"(a[2]), "r"(a[3]), "r"(b0), "r"(b1));
}

#define LDSM_X4(R, addr)                                                    \
    asm volatile("ldmatrix.sync.aligned.m8n8.x4.shared.b16 "                \
                 "{%0,%1,%2,%3}, [%4];"                                     \
                 : "=r"((R)[0]), "=r"((R)[1]), "=r"((R)[2]), "=r"((R)[3])   \
                 : "r"(addr))

#define CP_ASYNC16(dst, src)                                                \
    asm volatile("cp.async.cg.shared.global [%0], [%1], 16;"                \
                 :: "r"(dst), "l"(src))
#define CP_COMMIT()  asm volatile("cp.async.commit_group;" ::: "memory")
#define CP_WAIT0()   asm volatile("cp.async.wait_group 0;" ::: "memory")

// split fp32x4 into bf16 hi/lo and store (4 contiguous elems)
__device__ __forceinline__ void split4(__nv_bfloat16* hp, __nv_bfloat16* lp, float4 v) {
    __nv_bfloat16 h0 = __float2bfloat16(v.x);
    __nv_bfloat16 h1 = __float2bfloat16(v.y);
    __nv_bfloat16 h2 = __float2bfloat16(v.z);
    __nv_bfloat16 h3 = __float2bfloat16(v.w);
    __nv_bfloat162 hh0; hh0.x = h0; hh0.y = h1;
    __nv_bfloat162 hh1; hh1.x = h2; hh1.y = h3;
    *(__nv_bfloat162*)hp       = hh0;
    *((__nv_bfloat162*)hp + 1) = hh1;
    __nv_bfloat162 ll0, ll1;
    ll0.x = __float2bfloat16(v.x - __bfloat162float(h0));
    ll0.y = __float2bfloat16(v.y - __bfloat162float(h1));
    ll1.x = __float2bfloat16(v.z - __bfloat162float(h2));
    ll1.y = __float2bfloat16(v.w - __bfloat162float(h3));
    *(__nv_bfloat162*)lp       = ll0;
    *((__nv_bfloat162*)lp + 1) = ll1;
}

// ---------------------------------------------------------------------------
// bf16-split tensor-core GEMM: C[m,n] = sum_k A[m,k]*W[n,k] + bias[n]
// round_out != 0 -> store tf32-rounded output (for Q/K/V projections).
// ---------------------------------------------------------------------------
#define GTILE (128 * 24)   // bf16 elems per tile

__global__ __launch_bounds__(256, 2) void gemm_bf16s_kernel(
    const float* __restrict__ A, const float* __restrict__ W,
    const float* __restrict__ bias, float* __restrict__ C,
    int M, int N, int K, int round_out)
{
    __shared__ __nv_bfloat16 smem[2][4][GTILE];  // [stage][Ah,Al,Bh,Bl]

    const int tid  = threadIdx.x;
    const int lane = tid & 31;
    const int w    = tid >> 5;
    const int g    = lane >> 2;
    const int tg   = lane & 3;
    const int wr   = w >> 1;       // 0..3 (m)
    const int wc   = w & 1;        // 0..1 (n)

    const int m0 = blockIdx.y * 128;
    const int n0 = blockIdx.x * 128;

    const int lrow0 = tid >> 2;          // 0..63
    const int lrow1 = lrow0 + 64;        // 64..127
    const int col4  = tid & 3;

    const uint32_t smem_u32 = (uint32_t)__cvta_generic_to_shared(&smem[0][0][0]);

    float4 pa0, pa1, pw0, pw1;
    pa0 = *(const float4*)&A[(size_t)(m0 + lrow0) * K + col4 * 4];
    pa1 = *(const float4*)&A[(size_t)(m0 + lrow1) * K + col4 * 4];
    pw0 = *(const float4*)&W[(size_t)(n0 + lrow0) * K + col4 * 4];
    pw1 = *(const float4*)&W[(size_t)(n0 + lrow1) * K + col4 * 4];

    float acc[2][8][4];
#pragma unroll
    for (int mi = 0; mi < 2; mi++)
#pragma unroll
        for (int nt = 0; nt < 8; nt++)
#pragma unroll
            for (int j = 0; j < 4; j++) acc[mi][nt][j] = 0.f;

    const int arow = wr * 32;
    const int brow = wc * 64;

    const uint32_t a_off0 = ((arow + (lane & 15)) * 24 + ((lane >> 4) << 3)) * 2;
    const uint32_t a_off1 = a_off0 + 16 * 24 * 2;
    const uint32_t b_off  = ((brow + ((lane >> 4) << 3) + (lane & 7)) * 24
                             + (((lane >> 3) & 1) << 3)) * 2;

    {
        __nv_bfloat16* Ah = &smem[0][0][0];
        __nv_bfloat16* Al = &smem[0][1][0];
        __nv_bfloat16* Bh = &smem[0][2][0];
        __nv_bfloat16* Bl = &smem[0][3][0];
        split4(&Ah[lrow0 * 24 + col4 * 4], &Al[lrow0 * 24 + col4 * 4], pa0);
        split4(&Ah[lrow1 * 24 + col4 * 4], &Al[lrow1 * 24 + col4 * 4], pa1);
        split4(&Bh[lrow0 * 24 + col4 * 4], &Bl[lrow0 * 24 + col4 * 4], pw0);
        split4(&Bh[lrow1 * 24 + col4 * 4], &Bl[lrow1 * 24 + col4 * 4], pw1);
    }
    __syncthreads();

    const int nIter = K / 16;   // 48
    for (int it = 0; it < nIter; ++it) {
        const int cur = it & 1;
        const bool hasNext = (it + 1 < nIter);
        if (hasNext) {
            int kc = (it + 1) * 16 + col4 * 4;
            pa0 = *(const float4*)&A[(size_t)(m0 + lrow0) * K + kc];
            pa1 = *(const float4*)&A[(size_t)(m0 + lrow1) * K + kc];
            pw0 = *(const float4*)&W[(size_t)(n0 + lrow0) * K + kc];
            pw1 = *(const float4*)&W[(size_t)(n0 + lrow1) * K + kc];
        }

        {
            const uint32_t sAh = smem_u32 + (cur * 4 + 0) * (GTILE * 2);
            const uint32_t sAl = smem_u32 + (cur * 4 + 1) * (GTILE * 2);
            const uint32_t sBh = smem_u32 + (cur * 4 + 2) * (GTILE * 2);
            const uint32_t sBl = smem_u32 + (cur * 4 + 3) * (GTILE * 2);

            uint32_t ah[2][4], al[2][4];
            LDSM_X4(ah[0], sAh + a_off0);
            LDSM_X4(ah[1], sAh + a_off1);
            LDSM_X4(al[0], sAl + a_off0);
            LDSM_X4(al[1], sAl + a_off1);

#pragma unroll
            for (int p = 0; p < 4; p++) {
                uint32_t bh[4], bl[4];
                LDSM_X4(bh, sBh + b_off + p * (16 * 24 * 2));
                LDSM_X4(bl, sBl + b_off + p * (16 * 24 * 2));
#pragma unroll
                for (int j = 0; j < 2; j++) {
                    const int nt = p * 2 + j;
#pragma unroll
                    for (int mi = 0; mi < 2; mi++) {
                        mma16(acc[mi][nt], ah[mi], bh[2 * j], bh[2 * j + 1]);
                        mma16(acc[mi][nt], ah[mi], bl[2 * j], bl[2 * j + 1]);
                        mma16(acc[mi][nt], al[mi], bh[2 * j], bh[2 * j + 1]);
                    }
                }
            }
        }

        if (hasNext) {
            const int nxt = cur ^ 1;
            __nv_bfloat16* Ah = &smem[nxt][0][0];
            __nv_bfloat16* Al = &smem[nxt][1][0];
            __nv_bfloat16* Bh = &smem[nxt][2][0];
            __nv_bfloat16* Bl = &smem[nxt][3][0];
            split4(&Ah[lrow0 * 24 + col4 * 4], &Al[lrow0 * 24 + col4 * 4], pa0);
            split4(&Ah[lrow1 * 24 + col4 * 4], &Al[lrow1 * 24 + col4 * 4], pa1);
            split4(&Bh[lrow0 * 24 + col4 * 4], &Bl[lrow0 * 24 + col4 * 4], pw0);
            split4(&Bh[lrow1 * 24 + col4 * 4], &Bl[lrow1 * 24 + col4 * 4], pw1);
            __syncthreads();
        }
    }

    // epilogue: bias + (optional tf32 round) + store
#pragma unroll
    for (int nt = 0; nt < 8; nt++) {
        int c0 = n0 + brow + nt * 8 + tg * 2;
        float2 bb = *(const float2*)&bias[c0];
#pragma unroll
        for (int mi = 0; mi < 2; mi++) {
            int r0 = m0 + arow + mi * 16 + g;
            float2 o0 = make_float2(acc[mi][nt][0] + bb.x, acc[mi][nt][1] + bb.y);
            float2 o1 = make_float2(acc[mi][nt][2] + bb.x, acc[mi][nt][3] + bb.y);
            if (round_out) {
                o0.x = to_tf32(o0.x); o0.y = to_tf32(o0.y);
                o1.x = to_tf32(o1.x); o1.y = to_tf32(o1.y);
            }
            *(float2*)&C[(size_t)r0 * N + c0]       = o0;
            *(float2*)&C[(size_t)(r0 + 8) * N + c0] = o1;
        }
    }
}

// ---------------------------------------------------------------------------
// Flash attention v2: tf32 mma + ldmatrix fragments + cp.async double buffer.
// Br=64 q rows, Bc=32 keys/stage, 256 threads (8 warps, 4x2).
// Q/K/V in gmem are pre-rounded to tf32 by the projection GEMM epilogue.
// smem (floats): Qs 64x260 | Ks 2x32x260 | Vs 2x32x264 | Ps 64x36 | stats
// ---------------------------------------------------------------------------
#define AQK_STR 260
#define AV_STR  264
#define AP_STR  36
#define KS_OFF  (64 * AQK_STR)
#define VS_OFF  (KS_OFF + 2 * 32 * AQK_STR)
#define PS_OFF  (VS_OFF + 2 * 32 * AV_STR)
#define ST_OFF  (PS_OFF + 64 * AP_STR)
#define ATTN_SMEM_FLOATS (ST_OFF + 192)
#define ATTN_SMEM_BYTES  (ATTN_SMEM_FLOATS * 4)

__global__ __launch_bounds__(256) void attn_tc2_kernel(
    const float* __restrict__ Q, const float* __restrict__ K,
    const float* __restrict__ V, float* __restrict__ O)
{
    extern __shared__ float sm[];
    float* Ps   = sm + PS_OFF;
    float* sm_m = sm + ST_OFF;
    float* sm_l = sm_m + 64;
    float* sm_a = sm_l + 64;

    const uint32_t sbase = (uint32_t)__cvta_generic_to_shared(sm);

    const int tid  = threadIdx.x;
    const int lane = tid & 31;
    const int w    = tid >> 5;
    const int g    = lane >> 2;
    const int tg   = lane & 3;
    const int wr   = w >> 1;      // 0..3
    const int wc   = w & 1;       // 0..1

    const int bh = blockIdx.y;
    const int b  = bh / H_DIM;
    const int h  = bh % H_DIM;
    const int t0 = blockIdx.x * 64;
    const size_t head = (size_t)b * F_DIM + (size_t)h * DH;

    // ---- prologue: async-load Q tile + stage 0 of K/V ----
    {
        const int r = tid >> 6;           // base row step for Q chunks
        const int c = tid & 63;
#pragma unroll
        for (int i = 0; i < 4; i++) {     // 16 chunks: rows r + 4*i (4 rows per pass)
            int row = r + i * 4;
            const float* src = &Q[(size_t)(t0 + row) * ROW_STRIDE + head + c * 4];
            uint32_t dst = sbase + (uint32_t)(row * AQK_STR + c * 4) * 4;
            CP_ASYNC16(dst, src);
            row += 16;
            src = &Q[(size_t)(t0 + row) * ROW_STRIDE + head + c * 4];
            dst = sbase + (uint32_t)(row * AQK_STR + c * 4) * 4;
            CP_ASYNC16(dst, src);
            row += 16;
            src = &Q[(size_t)(t0 + row) * ROW_STRIDE + head + c * 4];
            dst = sbase + (uint32_t)(row * AQK_STR + c * 4) * 4;
            CP_ASYNC16(dst, src);
            row += 16;
            src = &Q[(size_t)(t0 + row) * ROW_STRIDE + head + c * 4];
            dst = sbase + (uint32_t)(row * AQK_STR + c * 4) * 4;
            CP_ASYNC16(dst, src);
        }
        // K/V stage 0: 32 rows x 64 chunks each, 8 per thread
        const int kr = tid >> 6, kc = tid & 63;
#pragma unroll
        for (int i = 0; i < 8; i++) {
            int row = kr + i * 4;
            size_t gaddr = (size_t)row * ROW_STRIDE + head + kc * 4;
            CP_ASYNC16(sbase + (uint32_t)(KS_OFF + row * AQK_STR + kc * 4) * 4, &K[gaddr]);
            CP_ASYNC16(sbase + (uint32_t)(VS_OFF + row * AV_STR  + kc * 4) * 4, &V[gaddr]);
        }
        CP_COMMIT();
    }

    if (tid < 64) { sm_m[tid] = -1e30f; sm_l[tid] = 0.f; }

    float oacc[16][4];
#pragma unroll
    for (int nt = 0; nt < 16; nt++)
#pragma unroll
        for (int j = 0; j < 4; j++) oacc[nt][j] = 0.f;

    const int rq = wr * 16, ck = wc * 16;   // S tile origin (rows x 16 cols)
    const int ro = wr * 16, co = wc * 128;  // O tile origin

    // ldmatrix lane-address components
    const int lr16 = lane & 15;
    const int lcA  = (lane >> 4) * 4;  // A-type col offset
    // Q A-frag base (byte addr, add k0*4)
    const uint32_t qoff = sbase + (uint32_t)((rq + lr16) * AQK_STR + lcA) * 4;
    // K B-frag: rows ck + ((lane>>4)<<3) + (lane&7), col ((lane>>3)&1)*4
    const uint32_t koff_l = (uint32_t)((ck + ((lane >> 4) << 3) + (lane & 7)) * AQK_STR
                                       + ((lane >> 3) & 1) * 4) * 4;
    // P A-frag base
    const uint32_t poff = sbase + (uint32_t)(PS_OFF + (ro + lr16) * AP_STR + lcA) * 4;

    const int sr = tid >> 2, qd = tid & 3;  // softmax mapping: row, 8-col group

    for (int t = 0; t < 64; ++t) {
        const int cur = t & 1;
        CP_WAIT0();
        __syncthreads();

        // prefetch next stage
        if (t + 1 < 64) {
            const int nxt = cur ^ 1;
            const int s0 = (t + 1) * 32;
            const int kr = tid >> 6, kc = tid & 63;
#pragma unroll
            for (int i = 0; i < 8; i++) {
                int row = kr + i * 4;
                size_t gaddr = (size_t)(s0 + row) * ROW_STRIDE + head + kc * 4;
                CP_ASYNC16(sbase + (uint32_t)(KS_OFF + (nxt * 32 + row) * AQK_STR + kc * 4) * 4, &K[gaddr]);
                CP_ASYNC16(sbase + (uint32_t)(VS_OFF + (nxt * 32 + row) * AV_STR  + kc * 4) * 4, &V[gaddr]);
            }
            CP_COMMIT();
        }

        // ---- S = Q K^T : warp tile 16x16, 2 n-blocks ----
        float sacc[2][4];
#pragma unroll
        for (int nt = 0; nt < 2; nt++)
#pragma unroll
            for (int j = 0; j < 4; j++) sacc[nt][j] = 0.f;

        const uint32_t kbase = sbase + (uint32_t)(KS_OFF + cur * 32 * AQK_STR) * 4 + koff_l;
#pragma unroll
        for (int k0 = 0; k0 < DH; k0 += 8) {
            uint32_t a[4], bb[4];
            LDSM_X4(a,  qoff  + k0 * 4);
            LDSM_X4(bb, kbase + k0 * 4);
            mma8(sacc[0], a[0], a[1], a[2], a[3], bb[0], bb[1]);
            mma8(sacc[1], a[0], a[1], a[2], a[3], bb[2], bb[3]);
        }

        // store S tile
#pragma unroll
        for (int nt = 0; nt < 2; nt++) {
            int c0 = ck + nt * 8 + tg * 2;
            *(float2*)&Ps[(rq + g)     * AP_STR + c0] = make_float2(sacc[nt][0], sacc[nt][1]);
            *(float2*)&Ps[(rq + g + 8) * AP_STR + c0] = make_float2(sacc[nt][2], sacc[nt][3]);
        }
        __syncthreads();

        // ---- online softmax: 4 threads per row, 8 cols each ----
        {
            float* row = &Ps[sr * AP_STR + qd * 8];
            float4 v0 = *(float4*)&row[0];
            float4 v1 = *(float4*)&row[4];
            const float sc = 0.125f;
            v0.x *= sc; v0.y *= sc; v0.z *= sc; v0.w *= sc;
            v1.x *= sc; v1.y *= sc; v1.z *= sc; v1.w *= sc;

            float mx = fmaxf(fmaxf(fmaxf(v0.x, v0.y), fmaxf(v0.z, v0.w)),
                             fmaxf(fmaxf(v1.x, v1.y), fmaxf(v1.z, v1.w)));
            mx = fmaxf(mx, __shfl_xor_sync(0xffffffffu, mx, 1));
            mx = fmaxf(mx, __shfl_xor_sync(0xffffffffu, mx, 2));

            float m_old = sm_m[sr];
            float m_new = fmaxf(m_old, mx);
            float alpha = __expf(m_old - m_new);

            v0.x = __expf(v0.x - m_new); v0.y = __expf(v0.y - m_new);
            v0.z = __expf(v0.z - m_new); v0.w = __expf(v0.w - m_new);
            v1.x = __expf(v1.x - m_new); v1.y = __expf(v1.y - m_new);
            v1.z = __expf(v1.z - m_new); v1.w = __expf(v1.w - m_new);

            float s = (v0.x + v0.y + v0.z + v0.w) + (v1.x + v1.y + v1.z + v1.w);
            s += __shfl_xor_sync(0xffffffffu, s, 1);
            s += __shfl_xor_sync(0xffffffffu, s, 2);

            v0.x = to_tf32(v0.x); v0.y = to_tf32(v0.y);
            v0.z = to_tf32(v0.z); v0.w = to_tf32(v0.w);
            v1.x = to_tf32(v1.x); v1.y = to_tf32(v1.y);
            v1.z = to_tf32(v1.z); v1.w = to_tf32(v1.w);
            *(float4*)&row[0] = v0;
            *(float4*)&row[4] = v1;

            if (qd == 0) {
                sm_m[sr] = m_new;
                sm_l[sr] = sm_l[sr] * alpha + s;
                sm_a[sr] = alpha;
            }
        }
        __syncthreads();

        // ---- rescale O, then O += P V : warp tile 16x128 ----
        {
            float al0 = sm_a[ro + g];
            float al1 = sm_a[ro + g + 8];
#pragma unroll
            for (int nt = 0; nt < 16; nt++) {
                oacc[nt][0] *= al0; oacc[nt][1] *= al0;
                oacc[nt][2] *= al1; oacc[nt][3] *= al1;
            }
        }
        const float* Vsc = sm + VS_OFF + cur * 32 * AV_STR;
#pragma unroll
        for (int k0 = 0; k0 < 32; k0 += 8) {
            uint32_t a[4];
            LDSM_X4(a, poff + k0 * 4);
            const float* vr0 = &Vsc[(k0 + tg)     * AV_STR + co + g];
            const float* vr1 = &Vsc[(k0 + tg + 4) * AV_STR + co + g];
#pragma unroll
            for (int nt = 0; nt < 16; nt++) {
                uint32_t b0 = __float_as_uint(vr0[nt * 8]);
                uint32_t b1 = __float_as_uint(vr1[nt * 8]);
                mma8(oacc[nt], a[0], a[1], a[2], a[3], b0, b1);
            }
        }
    }

    // ---- epilogue: normalize and write O ----
    {
        float il0 = 1.f / sm_l[ro + g];
        float il1 = 1.f / sm_l[ro + g + 8];
        size_t r0 = (size_t)(t0 + ro + g)     * ROW_STRIDE + head + co;
        size_t r1 = (size_t)(t0 + ro + g + 8) * ROW_STRIDE + head + co;
#pragma unroll
        for (int nt = 0; nt < 16; nt++) {
            int c0 = nt * 8 + tg * 2;
            *(float2*)&O[r0 + c0] = make_float2(oacc[nt][0] * il0, oacc[nt][1] * il0);
            *(float2*)&O[r1 + c0] = make_float2(oacc[nt][2] * il1, oacc[nt][3] * il1);
        }
    }
}

// ---------------------------------------------------------------------------
extern "C" void kernel_launch(void* const* d_in, const int* in_sizes, int n_in,
                              void* d_out, int out_size)
{
    const float* x  = (const float*)d_in[0];
    const float* Wq = (const float*)d_in[1];
    const float* bq = (const float*)d_in[2];
    const float* Wk = (const float*)d_in[3];
    const float* bk = (const float*)d_in[4];
    const float* Wv = (const float*)d_in[5];
    const float* bv = (const float*)d_in[6];
    const float* Wo = (const float*)d_in[7];
    const float* bo = (const float*)d_in[8];
    float* out = (float*)d_out;

    float *Qp, *Kp, *Vp, *Op;
    cudaGetSymbolAddress((void**)&Qp, g_Q);
    cudaGetSymbolAddress((void**)&Kp, g_K);
    cudaGetSymbolAddress((void**)&Vp, g_V);
    cudaGetSymbolAddress((void**)&Op, g_O);

    dim3 ggrid(F_DIM / 128, M_ROWS / 128);   // (6, 128)

    gemm_bf16s_kernel<<<ggrid, 256>>>(x, Wq, bq, Qp, M_ROWS, F_DIM, F_DIM, 1);
    gemm_bf16s_kernel<<<ggrid, 256>>>(x, Wk, bk, Kp, M_ROWS, F_DIM, F_DIM, 1);
    gemm_bf16s_kernel<<<ggrid, 256>>>(x, Wv, bv, Vp, M_ROWS, F_DIM, F_DIM, 1);

    cudaFuncSetAttribute(attn_tc2_kernel,
                         cudaFuncAttributeMaxDynamicSharedMemorySize,
                         ATTN_SMEM_BYTES);
    attn_tc2_kernel<<<dim3(T_DIM / 64, B_DIM * H_DIM), 256, ATTN_SMEM_BYTES>>>(
        Qp, Kp, Vp, Op);

    gemm_bf16s_kernel<<<ggrid, 256>>>(Op, Wo, bo, out, M_ROWS, F_DIM, F_DIM, 0);
}